// round 5
// baseline (speedup 1.0000x reference)
#include <cuda_runtime.h>
#include <cstdint>

#define N_NODES 250000
#define N_EDGES 4000000
#define NODE_F  4
#define HID     32
#define NN      50
#define NF      3
#define D_IN    9
#define OUT_C   53

typedef unsigned long long u64;

// Scratch (device globals)
__device__ float  g_accC[N_NODES];                 // 1 MB: Σ(hc + sc) per node
__device__ __align__(8) float2 g_accMS[N_NODES];   // 2 MB: Σ(hm+sm, hs+ss), tail nodes only
__device__ float g_conc[N_NODES];
__device__ float g_S;
__device__ int   g_ei_is64;
__device__ float g_sc, g_sm, g_ss;                 // b2 . W*[4:36]
// Per-j record (8 float4 = 128 B): {w0..w7 dup}, {w8,w8,b,b}, {.5uc,.5uc,.5um,.5um}, {.5us,.5us,0,0}, pad
__device__ __align__(16) float4 g_pack[HID * 8];   // 4 KB

__device__ __forceinline__ float softplusf(float x) {
    return fmaxf(x, 0.0f) + log1pf(expf(-fabsf(x)));
}
__device__ __forceinline__ u64 fma2(u64 a, u64 b, u64 c) {
    u64 d; asm("fma.rn.f32x2 %0,%1,%2,%3;" : "=l"(d) : "l"(a), "l"(b), "l"(c)); return d;
}
__device__ __forceinline__ u64 add2(u64 a, u64 b) {
    u64 d; asm("add.rn.f32x2 %0,%1,%2;" : "=l"(d) : "l"(a), "l"(b)); return d;
}
__device__ __forceinline__ u64 pack2(float lo, float hi) {
    u64 d; asm("mov.b64 %0,{%1,%2};" : "=l"(d) : "f"(lo), "f"(hi)); return d;
}
__device__ __forceinline__ void unpack2(float& lo, float& hi, u64 v) {
    asm("mov.b64 {%0,%1},%2;" : "=f"(lo), "=f"(hi) : "l"(v));
}
__device__ __forceinline__ u64 mk64(unsigned a, unsigned b) {
    u64 d; asm("mov.b64 %0,{%1,%2};" : "=l"(d) : "r"(a), "r"(b)); return d;
}

// ---------------------------------------------------------------------------
// Kernel A: detect ei dtype + build packed weight record (1 warp)
// ---------------------------------------------------------------------------
__global__ void prep_kernel(const int* __restrict__ ei32,
                            const float* __restrict__ W1,
                            const float* __restrict__ b1,
                            const float* __restrict__ W2,
                            const float* __restrict__ b2,
                            const float* __restrict__ Wc,
                            const float* __restrict__ Wmu,
                            const float* __restrict__ Wsig)
{
    const int k = threadIdx.x;  // hidden index j
    if (k == 0) {
        int z = 0;
        #pragma unroll
        for (int i = 1; i < 64; i += 2) z |= ei32[i];
        g_ei_is64 = (z == 0) ? 1 : 0;
        g_S = 0.0f;
    }
    float uc = 0.f, um = 0.f, us = 0.f;
    #pragma unroll
    for (int m = 0; m < HID; m++) {
        const float w = W2[k * HID + m];
        uc = fmaf(w, Wc[NODE_F + m],   uc);
        um = fmaf(w, Wmu[NODE_F + m],  um);
        us = fmaf(w, Wsig[NODE_F + m], us);
    }
    float w[D_IN];
    #pragma unroll
    for (int d = 0; d < D_IN; d++) w[d] = W1[d * HID + k];
    const float b = b1[k];
    float4* R = g_pack + k * 8;
    R[0] = make_float4(w[0], w[0], w[1], w[1]);
    R[1] = make_float4(w[2], w[2], w[3], w[3]);
    R[2] = make_float4(w[4], w[4], w[5], w[5]);
    R[3] = make_float4(w[6], w[6], w[7], w[7]);
    R[4] = make_float4(w[8], w[8], b, b);
    R[5] = make_float4(0.5f*uc, 0.5f*uc, 0.5f*um, 0.5f*um);
    R[6] = make_float4(0.5f*us, 0.5f*us, 0.f, 0.f);
    R[7] = make_float4(0.f, 0.f, 0.f, 0.f);

    float pc = b2[k] * Wc[NODE_F + k];
    float pm = b2[k] * Wmu[NODE_F + k];
    float ps = b2[k] * Wsig[NODE_F + k];
    #pragma unroll
    for (int off = 16; off > 0; off >>= 1) {
        pc += __shfl_xor_sync(0xffffffffu, pc, off);
        pm += __shfl_xor_sync(0xffffffffu, pm, off);
        ps += __shfl_xor_sync(0xffffffffu, ps, off);
    }
    if (k == 0) { g_sc = pc; g_sm = pm; g_ss = ps; }
}

// ---------------------------------------------------------------------------
// Kernel B: zero accumulators (tail-only for MS)
// ---------------------------------------------------------------------------
__global__ void zero_kernel() {
    const int i = blockIdx.x * blockDim.x + threadIdx.x;
    if (i < N_NODES) {
        g_accC[i] = 0.0f;
        if (i % NN >= NN - NF) g_accMS[i] = make_float2(0.f, 0.f);
    }
}

// ---------------------------------------------------------------------------
// Kernel C: per-edge MLP + projected scatter, 4 edges/thread via f32x2
// ---------------------------------------------------------------------------
__global__ __launch_bounds__(256) void edge_kernel(
    const float* __restrict__ x,
    const void* __restrict__ ei_raw,
    const float* __restrict__ ea)
{
    __shared__ __align__(16) float4 sP[HID * 8];  // 4 KB
    sP[threadIdx.x] = g_pack[threadIdx.x];
    __syncthreads();

    const int t = blockIdx.x * blockDim.x + threadIdx.x;
    if (t * 4 >= N_EDGES) return;

    int r[4], c[4];
    if (g_ei_is64) {
        const longlong2* ei = (const longlong2*)ei_raw;
        longlong2 r01 = __ldg(ei + t * 2), r23 = __ldg(ei + t * 2 + 1);
        longlong2 c01 = __ldg(ei + N_EDGES / 2 + t * 2), c23 = __ldg(ei + N_EDGES / 2 + t * 2 + 1);
        r[0] = (int)r01.x; r[1] = (int)r01.y; r[2] = (int)r23.x; r[3] = (int)r23.y;
        c[0] = (int)c01.x; c[1] = (int)c01.y; c[2] = (int)c23.x; c[3] = (int)c23.y;
    } else {
        const int4* ei = (const int4*)ei_raw;
        int4 rv = __ldg(ei + t);
        int4 cv = __ldg(ei + N_EDGES / 4 + t);
        r[0] = rv.x; r[1] = rv.y; r[2] = rv.z; r[3] = rv.w;
        c[0] = cv.x; c[1] = cv.y; c[2] = cv.z; c[3] = cv.w;
    }
    const float4 ev = __ldg(reinterpret_cast<const float4*>(ea) + t);

    const float4* x4 = reinterpret_cast<const float4*>(x);
    float4 xr0 = __ldg(x4 + r[0]), xr1 = __ldg(x4 + r[1]);
    float4 xr2 = __ldg(x4 + r[2]), xr3 = __ldg(x4 + r[3]);
    float4 xc0 = __ldg(x4 + c[0]), xc1 = __ldg(x4 + c[1]);
    float4 xc2 = __ldg(x4 + c[2]), xc3 = __ldg(x4 + c[3]);

    u64 in0[D_IN], in1[D_IN];
    in0[0] = pack2(xr0.x, xr1.x); in0[1] = pack2(xr0.y, xr1.y);
    in0[2] = pack2(xr0.z, xr1.z); in0[3] = pack2(xr0.w, xr1.w);
    in0[4] = pack2(xc0.x, xc1.x); in0[5] = pack2(xc0.y, xc1.y);
    in0[6] = pack2(xc0.z, xc1.z); in0[7] = pack2(xc0.w, xc1.w);
    in0[8] = pack2(ev.x, ev.y);
    in1[0] = pack2(xr2.x, xr3.x); in1[1] = pack2(xr2.y, xr3.y);
    in1[2] = pack2(xr2.z, xr3.z); in1[3] = pack2(xr2.w, xr3.w);
    in1[4] = pack2(xc2.x, xc3.x); in1[5] = pack2(xc2.y, xc3.y);
    in1[6] = pack2(xc2.z, xc3.z); in1[7] = pack2(xc2.w, xc3.w);
    in1[8] = pack2(ev.z, ev.w);

    const u64 ABS = 0x7FFFFFFF7FFFFFFFULL;
    u64 hc0 = 0, hm0 = 0, hs0 = 0, hc1 = 0, hm1 = 0, hs1 = 0;

    const uint4* sQ = reinterpret_cast<const uint4*>(sP);
    #pragma unroll
    for (int j = 0; j < HID; j++) {
        const uint4 q0 = sQ[j*8+0], q1 = sQ[j*8+1], q2 = sQ[j*8+2], q3 = sQ[j*8+3];
        const uint4 q4 = sQ[j*8+4], q5 = sQ[j*8+5], q6 = sQ[j*8+6];
        const u64 w0 = mk64(q0.x,q0.y), w1 = mk64(q0.z,q0.w);
        const u64 w2 = mk64(q1.x,q1.y), w3 = mk64(q1.z,q1.w);
        const u64 w4 = mk64(q2.x,q2.y), w5 = mk64(q2.z,q2.w);
        const u64 w6 = mk64(q3.x,q3.y), w7 = mk64(q3.z,q3.w);
        const u64 w8 = mk64(q4.x,q4.y), bb = mk64(q4.z,q4.w);
        const u64 uc = mk64(q5.x,q5.y), um = mk64(q5.z,q5.w);
        const u64 us = mk64(q6.x,q6.y);

        u64 a0 = bb, a1 = bb;
        a0 = fma2(in0[0], w0, a0); a1 = fma2(in1[0], w0, a1);
        a0 = fma2(in0[1], w1, a0); a1 = fma2(in1[1], w1, a1);
        a0 = fma2(in0[2], w2, a0); a1 = fma2(in1[2], w2, a1);
        a0 = fma2(in0[3], w3, a0); a1 = fma2(in1[3], w3, a1);
        a0 = fma2(in0[4], w4, a0); a1 = fma2(in1[4], w4, a1);
        a0 = fma2(in0[5], w5, a0); a1 = fma2(in1[5], w5, a1);
        a0 = fma2(in0[6], w6, a0); a1 = fma2(in1[6], w6, a1);
        a0 = fma2(in0[7], w7, a0); a1 = fma2(in1[7], w7, a1);
        a0 = fma2(in0[8], w8, a0); a1 = fma2(in1[8], w8, a1);

        const u64 t0 = add2(a0, a0 & ABS);   // 2*relu
        const u64 t1 = add2(a1, a1 & ABS);
        hc0 = fma2(t0, uc, hc0); hm0 = fma2(t0, um, hm0); hs0 = fma2(t0, us, hs0);
        hc1 = fma2(t1, uc, hc1); hm1 = fma2(t1, um, hm1); hs1 = fma2(t1, us, hs1);
    }

    float hcv[4], hmv[4], hsv[4];
    unpack2(hcv[0], hcv[1], hc0); unpack2(hcv[2], hcv[3], hc1);
    unpack2(hmv[0], hmv[1], hm0); unpack2(hmv[2], hmv[3], hm1);
    unpack2(hsv[0], hsv[1], hs0); unpack2(hsv[2], hsv[3], hs1);

    const float sc = g_sc, sm = g_sm, ss = g_ss;
    #pragma unroll
    for (int i = 0; i < 4; i++) {
        asm volatile("red.global.add.f32 [%0], %1;"
                     :: "l"(&g_accC[r[i]]), "f"(hcv[i] + sc) : "memory");
        if (r[i] % NN >= NN - NF) {
            asm volatile("red.global.add.v2.f32 [%0], {%1, %2};"
                         :: "l"(&g_accMS[r[i]]), "f"(hmv[i] + sm), "f"(hsv[i] + ss)
                         : "memory");
        }
    }
}

// ---------------------------------------------------------------------------
// Kernel D: per-node heads + conc sum
// ---------------------------------------------------------------------------
__global__ __launch_bounds__(256) void node_kernel(
    const float* __restrict__ x,
    const float* __restrict__ Wc,  const float* __restrict__ bc,
    const float* __restrict__ Wmu, const float* __restrict__ bmu,
    const float* __restrict__ Wsig,const float* __restrict__ bsig,
    const float* __restrict__ high,
    float* __restrict__ out)
{
    __shared__ float sWarp[8];
    const int i = blockIdx.x * blockDim.x + threadIdx.x;

    float concv = 0.0f;
    if (i < N_NODES) {
        const float  ac = g_accC[i];
        const float4 xi = __ldg(reinterpret_cast<const float4*>(x) + i);

        const float craw = xi.x * __ldg(Wc+0) + xi.y * __ldg(Wc+1)
                         + xi.z * __ldg(Wc+2) + xi.w * __ldg(Wc+3)
                         + ac + __ldg(bc) + 1e-10f;
        concv = softplusf(craw);
        g_conc[i] = concv;

        const int p = i % NN;
        if (p >= NN - NF) {
            const float2 ms = g_accMS[i];
            const float mraw = xi.x * __ldg(Wmu+0) + xi.y * __ldg(Wmu+1)
                             + xi.z * __ldg(Wmu+2) + xi.w * __ldg(Wmu+3)
                             + ms.x + __ldg(bmu) + 1e-20f;
            const float sraw = xi.x * __ldg(Wsig+0) + xi.y * __ldg(Wsig+1)
                             + xi.z * __ldg(Wsig+2) + xi.w * __ldg(Wsig+3)
                             + ms.y + __ldg(bsig) + 1e-20f;
            const float alpha = softplusf(mraw) + 1e-20f;
            const float beta  = softplusf(sraw) + 1e-20f;
            const int g = i / NN;
            const int j = p - (NN - NF);
            out[g * OUT_C + NN + j] = alpha / (alpha + beta) * __ldg(high + j);
        }
    }

    float s = concv;
    #pragma unroll
    for (int off = 16; off > 0; off >>= 1) s += __shfl_xor_sync(0xffffffffu, s, off);
    if ((threadIdx.x & 31) == 0) sWarp[threadIdx.x >> 5] = s;
    __syncthreads();
    if (threadIdx.x == 0) {
        float tsum = 0.f;
        #pragma unroll
        for (int w = 0; w < 8; w++) tsum += sWarp[w];
        atomicAdd(&g_S, tsum);
    }
}

// ---------------------------------------------------------------------------
// Kernel E: normalize conc
// ---------------------------------------------------------------------------
__global__ void final_kernel(float* __restrict__ out) {
    const int i = blockIdx.x * blockDim.x + threadIdx.x;
    if (i >= N_NODES) return;
    const float invS = 1.0f / (g_S + 1e-20f);
    out[(i / NN) * OUT_C + (i % NN)] = g_conc[i] * invS;
}

// ---------------------------------------------------------------------------
extern "C" void kernel_launch(void* const* d_in, const int* in_sizes, int n_in,
                              void* d_out, int out_size) {
    const float* x    = (const float*)d_in[0];
    const void*  ei   = d_in[1];
    const float* ea   = (const float*)d_in[2];
    const float* high = (const float*)d_in[3];
    const float* W1   = (const float*)d_in[4];
    const float* b1   = (const float*)d_in[5];
    const float* W2   = (const float*)d_in[6];
    const float* b2   = (const float*)d_in[7];
    const float* Wc   = (const float*)d_in[8];
    const float* bc   = (const float*)d_in[9];
    const float* Wmu  = (const float*)d_in[10];
    const float* bmu  = (const float*)d_in[11];
    const float* Wsig = (const float*)d_in[12];
    const float* bsig = (const float*)d_in[13];
    float* out = (float*)d_out;

    prep_kernel<<<1, 32>>>((const int*)ei, W1, b1, W2, b2, Wc, Wmu, Wsig);
    zero_kernel<<<(N_NODES + 255) / 256, 256>>>();
    edge_kernel<<<(N_EDGES / 4 + 255) / 256, 256>>>(x, ei, ea);
    node_kernel<<<(N_NODES + 255) / 256, 256>>>(x, Wc, bc, Wmu, bmu, Wsig, bsig, high, out);
    final_kernel<<<(N_NODES + 255) / 256, 256>>>(out);
}